// round 1
// baseline (speedup 1.0000x reference)
#include <cuda_runtime.h>
#include <math.h>

#define S_     56
#define B_     32
#define C_     1024
#define T_     48
#define H_     1024
#define EMB_   512
#define RANK_  128
#define VOCAB_ 32000
#define TM1    47
#define NROWS  (TM1*B_)     /* 1504 */
#define G4     (4*H_)       /* 4096 */

// ---------------- scratch (device globals; no allocation allowed) ----------
__device__ float g_emb[NROWS*EMB_];          // [t,b,EMB] embedded inputs
__device__ float g_gates_part[4][B_*G4];     // k-split partial gate sums
__device__ float g_h0[B_*H_], g_c0[B_*H_];
__device__ float g_h1[B_*H_], g_c1[B_*H_];
__device__ float g_ctx[B_*C_];
__device__ float g_feats[NROWS*(H_+C_)];     // [t,b, h1|ctx]
__device__ float g_hproj[NROWS*EMB_];
__device__ float g_tmp[NROWS*RANK_];
__device__ float g_sumexp[NROWS];
__device__ float g_lbl[NROWS];

// ---------------- init ------------------------------------------------------
__global__ void init_kernel(const float* __restrict__ enc_state, float* out) {
    int i = blockIdx.x * blockDim.x + threadIdx.x;   // 32768 threads
    if (i < B_*H_) {
        g_h0[i] = enc_state[i];
        g_h1[i] = enc_state[B_*H_ + i];
        g_c0[i] = 0.f; g_c1[i] = 0.f; g_ctx[i] = 0.f;
    }
    if (i < NROWS) g_sumexp[i] = 0.f;
    if (i == 0) out[0] = 0.f;
}

// ---------------- embedding: emb[t,b,:] = E[tok[b,t]] @ P -------------------
__global__ void embed_kernel(const float* __restrict__ E, const float* __restrict__ P,
                             const int* __restrict__ tok) {
    int t = blockIdx.x / B_;
    int b = blockIdx.x % B_;
    __shared__ float er[RANK_];
    int tid = threadIdx.x;                     // 128
    int token = tok[b*T_ + t];
    er[tid] = E[(size_t)token*RANK_ + tid];
    __syncthreads();
    float acc[4] = {0.f,0.f,0.f,0.f};
    for (int r = 0; r < RANK_; r++) {
        float a = er[r];
        const float* Pr = P + r*EMB_;
        #pragma unroll
        for (int j = 0; j < 4; j++) acc[j] += a * Pr[tid + j*128];
    }
    float* o = g_emb + (size_t)(t*B_ + b)*EMB_;
    #pragma unroll
    for (int j = 0; j < 4; j++) o[tid + j*128] = acc[j];
}

// ---------------- gates GEMM: [32,K] x [K,4096], k-split into 4 partials ----
// which==0: x=[emb_t | ctx | h0], W=[W0(1536 rows); U0], K=2560
// which==1: x=[h0 | h1],          W=[W1(1024 rows); U1], K=2048
__global__ void gates_gemm(int t, int which,
                           const float* __restrict__ Wa, const float* __restrict__ Wb) {
    __shared__ float xs[32*36];     // [k][row], padded
    __shared__ float ws[32*128];    // [k][col]
    const float *x0, *x1, *x2; int k0, k1, wKa, K;
    if (which == 0) { x0 = g_emb + (size_t)t*(B_*EMB_); k0 = EMB_; x1 = g_ctx; k1 = C_;
                      x2 = g_h0; wKa = EMB_ + C_; K = EMB_ + C_ + H_; }
    else            { x0 = g_h0; k0 = H_; x1 = g_h1; k1 = H_;
                      x2 = g_h1; wKa = H_; K = 2*H_; }

    int tid   = threadIdx.x;            // 256
    int cbase = blockIdx.x * 128;       // 32 col tiles
    int kc    = blockIdx.y;             // 4 k-chunks
    int kchunk = K >> 2;
    int kstart = kc * kchunk, kend = kstart + kchunk;
    int cg = tid & 31, rg = tid >> 5;
    int c0 = cg*4, r0 = rg*4;
    float acc[4][4] = {};

    for (int kb = kstart; kb < kend; kb += 32) {
        #pragma unroll
        for (int i = 0; i < 4; i++) {          // x tile: 32k x 32r
            int lin = tid + i*256;
            int kr = lin & 31, rr = lin >> 5;
            int gk = kb + kr;
            float v;
            if (gk < k0)            v = x0[rr*k0 + gk];
            else if (gk < k0 + k1)  v = x1[rr*k1 + (gk - k0)];
            else                    v = x2[rr*H_ + (gk - k0 - k1)];
            xs[kr*36 + rr] = v;
        }
        #pragma unroll
        for (int i = 0; i < 4; i++) {          // W tile: 32k x 128c (float4)
            int lin = tid + i*256;
            int c4 = lin & 31, kr = lin >> 5;
            int gk = kb + kr;
            const float* src = (gk < wKa) ? (Wa + (size_t)gk*G4)
                                          : (Wb + (size_t)(gk - wKa)*G4);
            float4 w4 = *(const float4*)(src + cbase + c4*4);
            *(float4*)(ws + kr*128 + c4*4) = w4;
        }
        __syncthreads();
        #pragma unroll
        for (int kk = 0; kk < 32; kk++) {
            float4 a = *(const float4*)(xs + kk*36 + r0);
            float4 b = *(const float4*)(ws + kk*128 + c0);
            float av[4] = {a.x,a.y,a.z,a.w};
            float bv[4] = {b.x,b.y,b.z,b.w};
            #pragma unroll
            for (int i = 0; i < 4; i++)
                #pragma unroll
                for (int j = 0; j < 4; j++) acc[i][j] += av[i]*bv[j];
        }
        __syncthreads();
    }
    float* outp = g_gates_part[kc];
    #pragma unroll
    for (int i = 0; i < 4; i++) {
        float4 v = make_float4(acc[i][0], acc[i][1], acc[i][2], acc[i][3]);
        *(float4*)(outp + (size_t)(r0 + i)*G4 + cbase + c0) = v;
    }
}

// ---------------- LSTM cell (sums 4 partials + bias) ------------------------
__global__ void lstm_cell(int t, int which, const float* __restrict__ bias) {
    int idx = blockIdx.x*256 + threadIdx.x;   // 32768
    int b = idx >> 10, j = idx & 1023;
    size_t gidx = (size_t)b*G4;
    float gi = bias[j], gf = bias[j+1024], gg = bias[j+2048], go = bias[j+3072];
    #pragma unroll
    for (int p = 0; p < 4; p++) {
        const float* g = g_gates_part[p] + gidx;
        gi += g[j]; gf += g[j+1024]; gg += g[j+2048]; go += g[j+3072];
    }
    float* h = which ? g_h1 : g_h0;
    float* c = which ? g_c1 : g_c0;
    float si = 1.f/(1.f + expf(-gi));
    float sf = 1.f/(1.f + expf(-gf));
    float so = 1.f/(1.f + expf(-go));
    float cn = sf*c[idx] + si*tanhf(gg);
    float hn = so*tanhf(cn);
    c[idx] = cn; h[idx] = hn;
    if (which) g_feats[(size_t)(t*B_ + b)*2048 + j] = hn;
}

// ---------------- attention --------------------------------------------------
__global__ void attn_kernel(int t, const float* __restrict__ enc,
                            const int* __restrict__ enc_lens) {
    int b = blockIdx.x;                  // 32 blocks, 256 threads
    __shared__ float hs[H_];
    __shared__ float sc[64];             // >= S_
    int tid = threadIdx.x;
    for (int i = tid; i < H_; i += 256) hs[i] = g_h1[b*H_ + i];
    __syncthreads();
    int w = tid >> 5, lane = tid & 31;
    int len = enc_lens[b];
    for (int s = w; s < S_; s += 8) {
        float a = 0.f;
        const float* e = enc + ((size_t)s*B_ + b)*C_;
        for (int cd = lane; cd < C_; cd += 32) a += e[cd]*hs[cd];
        #pragma unroll
        for (int o = 16; o; o >>= 1) a += __shfl_xor_sync(0xffffffffu, a, o);
        if (lane == 0) sc[s] = (s < len) ? a : -1.0e30f;
    }
    __syncthreads();
    if (w == 0) {                        // softmax over <=56 entries (one warp)
        float v0 = sc[lane];
        float v1 = (lane + 32 < S_) ? sc[lane + 32] : -1.0e30f;
        float m = fmaxf(v0, v1);
        #pragma unroll
        for (int o = 16; o; o >>= 1) m = fmaxf(m, __shfl_xor_sync(0xffffffffu, m, o));
        float e0 = expf(v0 - m);
        float e1 = (lane + 32 < S_) ? expf(v1 - m) : 0.f;
        float sum = e0 + e1;
        #pragma unroll
        for (int o = 16; o; o >>= 1) sum += __shfl_xor_sync(0xffffffffu, sum, o);
        sc[lane] = e0 / sum;
        if (lane + 32 < S_) sc[lane + 32] = e1 / sum;
    }
    __syncthreads();
    float* fc = g_feats + (size_t)(t*B_ + b)*2048 + 1024;
    for (int cd = tid; cd < C_; cd += 256) {
        float a = 0.f;
        #pragma unroll 8
        for (int s = 0; s < S_; s++) a += sc[s]*enc[((size_t)s*B_ + b)*C_ + cd];
        g_ctx[b*C_ + cd] = a;
        fc[cd] = a;
    }
}

// ---------------- hproj = tanh(feats @ Wo + bo) -------------------------------
__global__ void hproj_gemm(const float* __restrict__ Wo, const float* __restrict__ bo) {
    __shared__ float xs[32*36];
    __shared__ float ws[32*128];
    int tid = threadIdx.x;
    int cbase = blockIdx.x * 128;            // 4 tiles over 512
    int rbase = blockIdx.y * 32;             // 47 tiles over 1504
    int cg = tid & 31, rg = tid >> 5;
    int c0 = cg*4, r0 = rg*4;
    float acc[4][4] = {};
    for (int kb = 0; kb < 2048; kb += 32) {
        #pragma unroll
        for (int i = 0; i < 4; i++) {
            int lin = tid + i*256;
            int kr = lin & 31, rr = lin >> 5;
            xs[kr*36 + rr] = g_feats[(size_t)(rbase + rr)*2048 + kb + kr];
        }
        #pragma unroll
        for (int i = 0; i < 4; i++) {
            int lin = tid + i*256;
            int c4 = lin & 31, kr = lin >> 5;
            float4 w4 = *(const float4*)(Wo + (size_t)(kb + kr)*EMB_ + cbase + c4*4);
            *(float4*)(ws + kr*128 + c4*4) = w4;
        }
        __syncthreads();
        #pragma unroll
        for (int kk = 0; kk < 32; kk++) {
            float4 a = *(const float4*)(xs + kk*36 + r0);
            float4 b = *(const float4*)(ws + kk*128 + c0);
            float av[4] = {a.x,a.y,a.z,a.w};
            float bv[4] = {b.x,b.y,b.z,b.w};
            #pragma unroll
            for (int i = 0; i < 4; i++)
                #pragma unroll
                for (int j = 0; j < 4; j++) acc[i][j] += av[i]*bv[j];
        }
        __syncthreads();
    }
    #pragma unroll
    for (int i = 0; i < 4; i++)
        #pragma unroll
        for (int j = 0; j < 4; j++) {
            int col = cbase + c0 + j;
            g_hproj[(size_t)(rbase + r0 + i)*EMB_ + col] = tanhf(acc[i][j] + bo[col]);
        }
}

// ---------------- tmp = hproj @ P^T  ([1504,512] x [512,128]) -----------------
__global__ void tmp_gemm(const float* __restrict__ P) {
    __shared__ float xs[32*33];
    __shared__ float ws[32*33];
    int tid = threadIdx.x, lane = tid & 31, rg = tid >> 5, r0 = rg*4;
    int cbase = blockIdx.x * 32;             // 4 tiles over 128
    int rbase = blockIdx.y * 32;             // 47 tiles
    float a0=0.f, a1=0.f, a2=0.f, a3=0.f;
    for (int kb = 0; kb < 512; kb += 32) {
        #pragma unroll
        for (int i = 0; i < 4; i++) {
            int lin = tid + i*256;
            int kr = lin & 31, rr = lin >> 5;
            xs[kr*33 + rr] = g_hproj[(size_t)(rbase + rr)*EMB_ + kb + kr];
        }
        #pragma unroll
        for (int i = 0; i < 4; i++) {
            int lin = tid + i*256;
            int kr = lin & 31, j = lin >> 5;
            ws[kr*33 + j] = P[(size_t)(cbase + j)*EMB_ + kb + kr];   // transposed read
        }
        __syncthreads();
        #pragma unroll
        for (int kk = 0; kk < 32; kk++) {
            float bv = ws[kk*33 + lane];
            const float* xp = xs + kk*33 + r0;
            a0 += xp[0]*bv; a1 += xp[1]*bv; a2 += xp[2]*bv; a3 += xp[3]*bv;
        }
        __syncthreads();
    }
    g_tmp[(size_t)(rbase + r0 + 0)*RANK_ + cbase + lane] = a0;
    g_tmp[(size_t)(rbase + r0 + 1)*RANK_ + cbase + lane] = a1;
    g_tmp[(size_t)(rbase + r0 + 2)*RANK_ + cbase + lane] = a2;
    g_tmp[(size_t)(rbase + r0 + 3)*RANK_ + cbase + lane] = a3;
}

// ---------------- label logit: lbl[r] = dot(tmp[r], E[token]) -----------------
__global__ void label_kernel(const int* __restrict__ tok, const float* __restrict__ E) {
    int r = blockIdx.x*8 + (threadIdx.x >> 5);
    if (r >= NROWS) return;
    int lane = threadIdx.x & 31;
    int t = r / B_, b = r % B_;
    int lbl = tok[b*T_ + t + 1];
    float a = 0.f;
    for (int e = lane; e < RANK_; e += 32)
        a += g_tmp[(size_t)r*RANK_ + e] * E[(size_t)lbl*RANK_ + e];
    #pragma unroll
    for (int o = 16; o; o >>= 1) a += __shfl_xor_sync(0xffffffffu, a, o);
    if (lane == 0) g_lbl[r] = a;
}

// ---------------- sumexp over vocab: tile 32 rows x 128 vocab, K=128 ----------
__global__ void sumexp_gemm(const float* __restrict__ E) {
    __shared__ float ts[32*36];     // [k][row]
    __shared__ float es[32*132];    // [k][vocab], padded
    int tid = threadIdx.x;
    int vbase = blockIdx.x * 128;   // 250 tiles
    int rbase = blockIdx.y * 32;    // 47 tiles
    int cg = tid & 31, rg = tid >> 5;
    int v0 = cg*4, r0 = rg*4;
    float acc[4][4] = {};
    for (int kb = 0; kb < RANK_; kb += 32) {
        #pragma unroll
        for (int i = 0; i < 4; i++) {
            int lin = tid + i*256;
            int kr = lin & 31, rr = lin >> 5;
            ts[kr*36 + rr] = g_tmp[(size_t)(rbase + rr)*RANK_ + kb + kr];
        }
        #pragma unroll
        for (int i = 0; i < 16; i++) {
            int lin = tid + i*256;              // 4096 elements
            int kr = lin & 31, vv = lin >> 5;
            es[kr*132 + vv] = E[(size_t)(vbase + vv)*RANK_ + kb + kr];
        }
        __syncthreads();
        #pragma unroll
        for (int kk = 0; kk < 32; kk++) {
            float4 a = *(const float4*)(ts + kk*36 + r0);
            float4 b = *(const float4*)(es + kk*132 + v0);
            float av[4] = {a.x,a.y,a.z,a.w};
            float bv[4] = {b.x,b.y,b.z,b.w};
            #pragma unroll
            for (int i = 0; i < 4; i++)
                #pragma unroll
                for (int j = 0; j < 4; j++) acc[i][j] += av[i]*bv[j];
        }
        __syncthreads();
    }
    #pragma unroll
    for (int i = 0; i < 4; i++) {
        float s = expf(acc[i][0]) + expf(acc[i][1]) + expf(acc[i][2]) + expf(acc[i][3]);
        #pragma unroll
        for (int o = 16; o; o >>= 1) s += __shfl_xor_sync(0xffffffffu, s, o);
        if ((tid & 31) == 0) atomicAdd(&g_sumexp[rbase + r0 + i], s);
    }
}

// ---------------- final loss ---------------------------------------------------
__global__ void loss_kernel(const int* __restrict__ tgt_lens, float* out) {
    int r = blockIdx.x*blockDim.x + threadIdx.x;
    if (r >= NROWS) return;
    int t = r / B_, b = r % B_;
    if (t < tgt_lens[b] - 1) {
        float nll = logf(g_sumexp[r]) - g_lbl[r];
        atomicAdd(out, nll);
    }
}

// ---------------- launch --------------------------------------------------------
extern "C" void kernel_launch(void* const* d_in, const int* in_sizes, int n_in,
                              void* d_out, int out_size) {
    const float* encoded   = (const float*)d_in[0];
    const float* enc_state = (const float*)d_in[1];
    const int*   tok       = (const int*)  d_in[2];
    const int*   enc_lens  = (const int*)  d_in[3];
    const int*   tgt_lens  = (const int*)  d_in[4];
    const float* E         = (const float*)d_in[5];
    const float* P         = (const float*)d_in[6];
    const float* W0        = (const float*)d_in[7];
    const float* U0        = (const float*)d_in[8];
    const float* b0        = (const float*)d_in[9];
    const float* W1        = (const float*)d_in[10];
    const float* U1        = (const float*)d_in[11];
    const float* b1        = (const float*)d_in[12];
    const float* Wo        = (const float*)d_in[13];
    const float* bo        = (const float*)d_in[14];
    float* out = (float*)d_out;

    init_kernel<<<128, 256>>>(enc_state, out);
    embed_kernel<<<NROWS, 128>>>(E, P, tok);

    for (int t = 0; t < TM1; t++) {
        gates_gemm<<<dim3(32, 4), 256>>>(t, 0, W0, U0);
        lstm_cell<<<128, 256>>>(t, 0, b0);
        gates_gemm<<<dim3(32, 4), 256>>>(t, 1, W1, U1);
        lstm_cell<<<128, 256>>>(t, 1, b1);
        attn_kernel<<<B_, 256>>>(t, encoded, enc_lens);
    }

    hproj_gemm<<<dim3(4, 47), 256>>>(Wo, bo);
    tmp_gemm<<<dim3(4, 47), 256>>>(P);
    label_kernel<<<188, 256>>>(tok, E);
    sumexp_gemm<<<dim3(250, 47), 256>>>(E);
    loss_kernel<<<6, 256>>>(tgt_lens, out);
}

// round 2
// speedup vs baseline: 2.8351x; 2.8351x over previous
#include <cuda_runtime.h>
#include <cuda_bf16.h>
#include <math.h>
#include <stdint.h>

#define S_     56
#define B_     32
#define C_     1024
#define T_     48
#define H_     1024
#define EMB_   512
#define RANK_  128
#define VOCAB_ 32000
#define TM1    47
#define NROWS  (TM1*B_)     /* 1504 */
#define G4     (4*H_)       /* 4096 */
#define K0_    2560         /* EMB + C + H */
#define K1_    2048         /* 2H */

// ---------------- scratch (device globals) ----------------------------------
__device__ __align__(16) __nv_bfloat16 g_W0b[K0_*G4];     // [k][4096] (W0;U0)
__device__ __align__(16) __nv_bfloat16 g_W1b[K1_*G4];     // [k][4096] (W1;U1)
__device__ __align__(16) __nv_bfloat16 g_Eb[VOCAB_*RANK_];
__device__ __align__(16) __nv_bfloat16 g_embB[TM1*B_*EMB_];
__device__ __align__(16) __nv_bfloat16 g_xa[B_*K0_];      // [b][emb|ctx|h0]
__device__ __align__(16) __nv_bfloat16 g_xb[B_*K1_];      // [b][h0|h1]
__device__ __align__(16) __nv_bfloat16 g_tmpB[1536*RANK_];
__device__ float g_gates_part[4][B_*G4];
__device__ float g_h0[B_*H_], g_c0[B_*H_];
__device__ float g_h1[B_*H_], g_c1[B_*H_];
__device__ float g_feats[NROWS*(H_+C_)];
__device__ float g_hproj[NROWS*EMB_];
__device__ float g_tmp[NROWS*RANK_];
__device__ float g_sumexp[1536];
__device__ float g_lbl[NROWS];

// ---------------- mma helpers ------------------------------------------------
__device__ __forceinline__ void ldsm_x4(uint32_t* r, const void* p) {
    uint32_t a = (uint32_t)__cvta_generic_to_shared(p);
    asm volatile("ldmatrix.sync.aligned.m8n8.x4.shared.b16 {%0,%1,%2,%3}, [%4];"
        : "=r"(r[0]), "=r"(r[1]), "=r"(r[2]), "=r"(r[3]) : "r"(a));
}
__device__ __forceinline__ void ldsm_x4_t(uint32_t* r, const void* p) {
    uint32_t a = (uint32_t)__cvta_generic_to_shared(p);
    asm volatile("ldmatrix.sync.aligned.m8n8.x4.trans.shared.b16 {%0,%1,%2,%3}, [%4];"
        : "=r"(r[0]), "=r"(r[1]), "=r"(r[2]), "=r"(r[3]) : "r"(a));
}
__device__ __forceinline__ void mma_bf16(float* d, const uint32_t* a, uint32_t b0, uint32_t b1) {
    asm volatile("mma.sync.aligned.m16n8k16.row.col.f32.bf16.bf16.f32 "
        "{%0,%1,%2,%3},{%4,%5,%6,%7},{%8,%9},{%0,%1,%2,%3};"
        : "+f"(d[0]), "+f"(d[1]), "+f"(d[2]), "+f"(d[3])
        : "r"(a[0]), "r"(a[1]), "r"(a[2]), "r"(a[3]), "r"(b0), "r"(b1));
}

// ---------------- fp32 -> bf16 weight conversion ------------------------------
#define W0E (K0_*G4)
#define W1E (K1_*G4)
#define EE  (VOCAB_*RANK_)
#define CVT_TOT (W0E + W1E + EE)
__global__ void convert_kernel(const float* __restrict__ W0, const float* __restrict__ U0,
                               const float* __restrict__ W1, const float* __restrict__ U1,
                               const float* __restrict__ E) {
    long long i4 = ((long long)blockIdx.x*blockDim.x + threadIdx.x) * 4;
    if (i4 >= CVT_TOT) return;
    const float* src; __nv_bfloat16* dst;
    if (i4 < W0E) {
        long long o = i4;
        src = (o < (long long)1536*G4) ? (W0 + o) : (U0 + o - (long long)1536*G4);
        dst = g_W0b + o;
    } else if (i4 < W0E + W1E) {
        long long o = i4 - W0E;
        src = (o < (long long)1024*G4) ? (W1 + o) : (U1 + o - (long long)1024*G4);
        dst = g_W1b + o;
    } else {
        long long o = i4 - W0E - W1E;
        src = E + o; dst = g_Eb + o;
    }
    float4 v = *(const float4*)src;
    __nv_bfloat162* d2 = (__nv_bfloat162*)dst;
    d2[0] = __nv_bfloat162(__float2bfloat16_rn(v.x), __float2bfloat16_rn(v.y));
    d2[1] = __nv_bfloat162(__float2bfloat16_rn(v.z), __float2bfloat16_rn(v.w));
}

// ---------------- embedding: embB[t,b,:] = bf16(E[tok[b,t]] @ P) --------------
__global__ void embed_kernel(const float* __restrict__ E, const float* __restrict__ P,
                             const int* __restrict__ tok) {
    int t = blockIdx.x / B_;
    int b = blockIdx.x % B_;
    __shared__ float er[RANK_];
    int tid = threadIdx.x;                     // 128
    int token = tok[b*T_ + t];
    er[tid] = E[(size_t)token*RANK_ + tid];
    __syncthreads();
    float acc[4] = {0.f,0.f,0.f,0.f};
    for (int r = 0; r < RANK_; r++) {
        float a = er[r];
        const float* Pr = P + r*EMB_;
        #pragma unroll
        for (int j = 0; j < 4; j++) acc[j] += a * Pr[tid + j*128];
    }
    __nv_bfloat16* o = g_embB + (size_t)(t*B_ + b)*EMB_;
    #pragma unroll
    for (int j = 0; j < 4; j++) o[tid + j*128] = __float2bfloat16_rn(acc[j]);
}

// ---------------- init (runs AFTER embed) -------------------------------------
__global__ void init_kernel(const float* __restrict__ enc_state, float* out) {
    int i = blockIdx.x * blockDim.x + threadIdx.x;   // 32768 threads
    if (i < B_*H_) {
        int b = i >> 10, j = i & 1023;
        float h0v = enc_state[i];
        float h1v = enc_state[B_*H_ + i];
        g_h0[i] = h0v; g_h1[i] = h1v;
        g_c0[i] = 0.f; g_c1[i] = 0.f;
        __nv_bfloat16 h0b = __float2bfloat16_rn(h0v);
        __nv_bfloat16 h1b = __float2bfloat16_rn(h1v);
        g_xa[b*K0_ + 1536 + j] = h0b;
        g_xb[b*K1_ + j]        = h0b;
        g_xb[b*K1_ + 1024 + j] = h1b;
        g_xa[b*K0_ + 512 + j]  = __float2bfloat16_rn(0.f);   // ctx = 0
        if (j < EMB_) g_xa[b*K0_ + j] = g_embB[b*EMB_ + j];  // emb[t=0]
    }
    if (i < 1536) g_sumexp[i] = 0.f;
    if (i == 0) out[0] = 0.f;
}

// ---------------- gates GEMM (bf16 tensor cores) -------------------------------
// out tile 32 x 64 per block; grid (64 col-tiles, 4 k-splits); 128 threads
__global__ void gates_mma(int which) {
    __shared__ __nv_bfloat16 xs[32][72];
    __shared__ __nv_bfloat16 ws[64][72];
    const __nv_bfloat16 *X, *Wb; int K, iters;
    if (which == 0) { X = g_xa; Wb = g_W0b; K = K0_; iters = 10; }
    else            { X = g_xb; Wb = g_W1b; K = K1_; iters = 8;  }
    int tid = threadIdx.x, lane = tid & 31, w = tid >> 5;
    int cbase  = blockIdx.x * 64;
    int kstart = blockIdx.y * (K >> 2);
    int n0 = w * 16;
    float acc[2][2][4] = {};

    for (int it = 0; it < iters; it++) {
        int kb = kstart + it*64;
        {   // x tile: 32 x 64
            int c = tid * 2;
            #pragma unroll
            for (int q = 0; q < 2; q++, c++) {
                int row = c >> 3, kc = c & 7;
                *(uint4*)&xs[row][kc*8] = *(const uint4*)&X[row*K + kb + kc*8];
            }
        }
        #pragma unroll
        for (int q = 0; q < 4; q++) {       // W tile: 64 x 64
            int c = tid + q*128;
            int row = c >> 3, cc = c & 7;
            *(uint4*)&ws[row][cc*8] = *(const uint4*)&Wb[(size_t)(kb + row)*G4 + cbase + cc*8];
        }
        __syncthreads();
        #pragma unroll
        for (int ks = 0; ks < 4; ks++) {
            uint32_t a0[4], a1[4], b[4];
            ldsm_x4(a0, &xs[(lane & 15)][ks*16 + (lane >> 4)*8]);
            ldsm_x4(a1, &xs[16 + (lane & 15)][ks*16 + (lane >> 4)*8]);
            ldsm_x4_t(b, &ws[ks*16 + (lane & 15)][n0 + (lane >> 4)*8]);
            mma_bf16(acc[0][0], a0, b[0], b[1]);
            mma_bf16(acc[0][1], a0, b[2], b[3]);
            mma_bf16(acc[1][0], a1, b[0], b[1]);
            mma_bf16(acc[1][1], a1, b[2], b[3]);
        }
        __syncthreads();
    }
    float* gp = g_gates_part[blockIdx.y];
    #pragma unroll
    for (int mt = 0; mt < 2; mt++)
        #pragma unroll
        for (int nt = 0; nt < 2; nt++) {
            int row = mt*16 + (lane >> 2);
            int col = cbase + n0 + nt*8 + 2*(lane & 3);
            *(float2*)&gp[(size_t)row*G4 + col]     = make_float2(acc[mt][nt][0], acc[mt][nt][1]);
            *(float2*)&gp[(size_t)(row+8)*G4 + col] = make_float2(acc[mt][nt][2], acc[mt][nt][3]);
        }
}

// ---------------- LSTM cell (sums 4 partials + bias), vectorized x4 -----------
__device__ __forceinline__ float sig_(float x) { return 1.f/(1.f + __expf(-x)); }

__global__ void lstm_cell(int t, int which, const float* __restrict__ bias) {
    int idx = blockIdx.x*blockDim.x + threadIdx.x;    // 8192 threads
    int i4 = idx * 4;
    int b = i4 >> 10, j = i4 & 1023;
    size_t gbase = (size_t)b*G4;
    float4 gi = *(const float4*)&bias[j];
    float4 gf = *(const float4*)&bias[j+1024];
    float4 gg = *(const float4*)&bias[j+2048];
    float4 go = *(const float4*)&bias[j+3072];
    #pragma unroll
    for (int p = 0; p < 4; p++) {
        const float* g = g_gates_part[p] + gbase;
        float4 x;
        x = *(const float4*)&g[j];      gi.x+=x.x; gi.y+=x.y; gi.z+=x.z; gi.w+=x.w;
        x = *(const float4*)&g[j+1024]; gf.x+=x.x; gf.y+=x.y; gf.z+=x.z; gf.w+=x.w;
        x = *(const float4*)&g[j+2048]; gg.x+=x.x; gg.y+=x.y; gg.z+=x.z; gg.w+=x.w;
        x = *(const float4*)&g[j+3072]; go.x+=x.x; go.y+=x.y; go.z+=x.z; go.w+=x.w;
    }
    float* h = which ? g_h1 : g_h0;
    float* c = which ? g_c1 : g_c0;
    float4 cv = *(float4*)&c[i4];
    float cn0 = sig_(gf.x)*cv.x + sig_(gi.x)*tanhf(gg.x);
    float cn1 = sig_(gf.y)*cv.y + sig_(gi.y)*tanhf(gg.y);
    float cn2 = sig_(gf.z)*cv.z + sig_(gi.z)*tanhf(gg.z);
    float cn3 = sig_(gf.w)*cv.w + sig_(gi.w)*tanhf(gg.w);
    float4 hn = make_float4(sig_(go.x)*tanhf(cn0), sig_(go.y)*tanhf(cn1),
                            sig_(go.z)*tanhf(cn2), sig_(go.w)*tanhf(cn3));
    *(float4*)&c[i4] = make_float4(cn0, cn1, cn2, cn3);
    *(float4*)&h[i4] = hn;
    __nv_bfloat162 h01 = __nv_bfloat162(__float2bfloat16_rn(hn.x), __float2bfloat16_rn(hn.y));
    __nv_bfloat162 h23 = __nv_bfloat162(__float2bfloat16_rn(hn.z), __float2bfloat16_rn(hn.w));
    if (!which) {
        *(__nv_bfloat162*)&g_xa[b*K0_ + 1536 + j]     = h01;
        *(__nv_bfloat162*)&g_xa[b*K0_ + 1536 + j + 2] = h23;
        *(__nv_bfloat162*)&g_xb[b*K1_ + j]            = h01;
        *(__nv_bfloat162*)&g_xb[b*K1_ + j + 2]        = h23;
    } else {
        *(__nv_bfloat162*)&g_xb[b*K1_ + 1024 + j]     = h01;
        *(__nv_bfloat162*)&g_xb[b*K1_ + 1024 + j + 2] = h23;
        *(float4*)&g_feats[(size_t)(t*B_ + b)*2048 + j] = hn;
    }
}

// ---------------- attention ----------------------------------------------------
__global__ void attn_kernel(int t, const float* __restrict__ enc,
                            const int* __restrict__ enc_lens) {
    int b = blockIdx.x;                  // 32 blocks, 256 threads
    __shared__ float hs[H_];
    __shared__ float sc[64];
    int tid = threadIdx.x;
    for (int i = tid; i < H_; i += 256) hs[i] = g_h1[b*H_ + i];
    __syncthreads();
    int w = tid >> 5, lane = tid & 31;
    int len = enc_lens[b];
    for (int s = w; s < S_; s += 8) {
        float a = 0.f;
        const float* e = enc + ((size_t)s*B_ + b)*C_;
        for (int cd = lane; cd < C_; cd += 32) a += e[cd]*hs[cd];
        #pragma unroll
        for (int o = 16; o; o >>= 1) a += __shfl_xor_sync(0xffffffffu, a, o);
        if (lane == 0) sc[s] = (s < len) ? a : -1.0e30f;
    }
    __syncthreads();
    if (w == 0) {
        float v0 = sc[lane];
        float v1 = (lane + 32 < S_) ? sc[lane + 32] : -1.0e30f;
        float m = fmaxf(v0, v1);
        #pragma unroll
        for (int o = 16; o; o >>= 1) m = fmaxf(m, __shfl_xor_sync(0xffffffffu, m, o));
        float e0 = __expf(v0 - m);
        float e1 = (lane + 32 < S_) ? __expf(v1 - m) : 0.f;
        float sum = e0 + e1;
        #pragma unroll
        for (int o = 16; o; o >>= 1) sum += __shfl_xor_sync(0xffffffffu, sum, o);
        sc[lane] = e0 / sum;
        if (lane + 32 < S_) sc[lane + 32] = e1 / sum;
    }
    __syncthreads();
    float* fc = g_feats + (size_t)(t*B_ + b)*2048 + 1024;
    for (int cd = tid; cd < C_; cd += 256) {
        float a = 0.f;
        #pragma unroll 8
        for (int s = 0; s < S_; s++) a += sc[s]*enc[((size_t)s*B_ + b)*C_ + cd];
        fc[cd] = a;
        g_xa[b*K0_ + 512 + cd] = __float2bfloat16_rn(a);
    }
    if (t + 1 < TM1) {   // stage next step's embedding into xa
        const __nv_bfloat16* src = g_embB + ((size_t)(t+1)*B_ + b)*EMB_;
        for (int k = tid; k < EMB_; k += 256) g_xa[b*K0_ + k] = src[k];
    }
}

// ---------------- hproj = tanh(feats @ Wo + bo) (fp32) --------------------------
__global__ void hproj_gemm(const float* __restrict__ Wo, const float* __restrict__ bo) {
    __shared__ float xs[32*36];
    __shared__ float ws[32*128];
    int tid = threadIdx.x;
    int cbase = blockIdx.x * 128;
    int rbase = blockIdx.y * 32;
    int cg = tid & 31, rg = tid >> 5;
    int c0 = cg*4, r0 = rg*4;
    float acc[4][4] = {};
    for (int kb = 0; kb < 2048; kb += 32) {
        #pragma unroll
        for (int i = 0; i < 4; i++) {
            int lin = tid + i*256;
            int kr = lin & 31, rr = lin >> 5;
            xs[kr*36 + rr] = g_feats[(size_t)(rbase + rr)*2048 + kb + kr];
        }
        #pragma unroll
        for (int i = 0; i < 4; i++) {
            int lin = tid + i*256;
            int c4 = lin & 31, kr = lin >> 5;
            float4 w4 = *(const float4*)(Wo + (size_t)(kb + kr)*EMB_ + cbase + c4*4);
            *(float4*)(ws + kr*128 + c4*4) = w4;
        }
        __syncthreads();
        #pragma unroll
        for (int kk = 0; kk < 32; kk++) {
            float4 a = *(const float4*)(xs + kk*36 + r0);
            float4 b = *(const float4*)(ws + kk*128 + c0);
            float av[4] = {a.x,a.y,a.z,a.w};
            float bv[4] = {b.x,b.y,b.z,b.w};
            #pragma unroll
            for (int i = 0; i < 4; i++)
                #pragma unroll
                for (int j = 0; j < 4; j++) acc[i][j] += av[i]*bv[j];
        }
        __syncthreads();
    }
    #pragma unroll
    for (int i = 0; i < 4; i++)
        #pragma unroll
        for (int j = 0; j < 4; j++) {
            int col = cbase + c0 + j;
            g_hproj[(size_t)(rbase + r0 + i)*EMB_ + col] = tanhf(acc[i][j] + bo[col]);
        }
}

// ---------------- tmp = hproj @ P^T, also bf16 copy ------------------------------
__global__ void tmp_gemm(const float* __restrict__ P) {
    __shared__ float xs[32*33];
    __shared__ float ws[32*33];
    int tid = threadIdx.x, lane = tid & 31, rg = tid >> 5, r0 = rg*4;
    int cbase = blockIdx.x * 32;
    int rbase = blockIdx.y * 32;
    float a0=0.f, a1=0.f, a2=0.f, a3=0.f;
    for (int kb = 0; kb < 512; kb += 32) {
        #pragma unroll
        for (int i = 0; i < 4; i++) {
            int lin = tid + i*256;
            int kr = lin & 31, rr = lin >> 5;
            xs[kr*33 + rr] = g_hproj[(size_t)(rbase + rr)*EMB_ + kb + kr];
        }
        #pragma unroll
        for (int i = 0; i < 4; i++) {
            int lin = tid + i*256;
            int kr = lin & 31, j = lin >> 5;
            ws[kr*33 + j] = P[(size_t)(cbase + j)*EMB_ + kb + kr];
        }
        __syncthreads();
        #pragma unroll
        for (int kk = 0; kk < 32; kk++) {
            float bv = ws[kk*33 + lane];
            const float* xp = xs + kk*33 + r0;
            a0 += xp[0]*bv; a1 += xp[1]*bv; a2 += xp[2]*bv; a3 += xp[3]*bv;
        }
        __syncthreads();
    }
    int c = cbase + lane;
    g_tmp[(size_t)(rbase + r0 + 0)*RANK_ + c] = a0;
    g_tmp[(size_t)(rbase + r0 + 1)*RANK_ + c] = a1;
    g_tmp[(size_t)(rbase + r0 + 2)*RANK_ + c] = a2;
    g_tmp[(size_t)(rbase + r0 + 3)*RANK_ + c] = a3;
    g_tmpB[(size_t)(rbase + r0 + 0)*RANK_ + c] = __float2bfloat16_rn(a0);
    g_tmpB[(size_t)(rbase + r0 + 1)*RANK_ + c] = __float2bfloat16_rn(a1);
    g_tmpB[(size_t)(rbase + r0 + 2)*RANK_ + c] = __float2bfloat16_rn(a2);
    g_tmpB[(size_t)(rbase + r0 + 3)*RANK_ + c] = __float2bfloat16_rn(a3);
}

// ---------------- label logit (fp32) ---------------------------------------------
__global__ void label_kernel(const int* __restrict__ tok, const float* __restrict__ E) {
    int r = blockIdx.x*8 + (threadIdx.x >> 5);
    if (r >= NROWS) return;
    int lane = threadIdx.x & 31;
    int t = r / B_, b = r % B_;
    int lbl = tok[b*T_ + t + 1];
    float a = 0.f;
    for (int e = lane; e < RANK_; e += 32)
        a += g_tmp[(size_t)r*RANK_ + e] * E[(size_t)lbl*RANK_ + e];
    #pragma unroll
    for (int o = 16; o; o >>= 1) a += __shfl_xor_sync(0xffffffffu, a, o);
    if (lane == 0) g_lbl[r] = a;
}

// ---------------- sumexp via bf16 mma: 64 rows x 64 vocab per block ---------------
__global__ void sumexp_mma() {
    __shared__ __nv_bfloat16 ts[64][136];
    __shared__ __nv_bfloat16 es[64][136];
    int tid = threadIdx.x, lane = tid & 31, w = tid >> 5;
    int vbase = blockIdx.x * 64, rbase = blockIdx.y * 64;
    #pragma unroll
    for (int q = 0; q < 8; q++) {
        int c = tid + q*128;
        int row = c >> 4, kc = c & 15;
        *(uint4*)&ts[row][kc*8] = *(const uint4*)&g_tmpB[(size_t)(rbase + row)*RANK_ + kc*8];
        *(uint4*)&es[row][kc*8] = *(const uint4*)&g_Eb[(size_t)(vbase + row)*RANK_ + kc*8];
    }
    __syncthreads();
    int m0 = (w & 1)*32, nb = (w >> 1)*32;
    float acc[2][4][4] = {};
    #pragma unroll
    for (int ks = 0; ks < 8; ks++) {
        uint32_t a0[4], a1[4], bA[4], bB[4];
        ldsm_x4(a0, &ts[m0 + (lane & 15)][ks*16 + (lane >> 4)*8]);
        ldsm_x4(a1, &ts[m0 + 16 + (lane & 15)][ks*16 + (lane >> 4)*8]);
        ldsm_x4(bA, &es[nb + (lane & 15)][ks*16 + (lane >> 4)*8]);
        ldsm_x4(bB, &es[nb + 16 + (lane & 15)][ks*16 + (lane >> 4)*8]);
        mma_bf16(acc[0][0], a0, bA[0], bA[2]);
        mma_bf16(acc[0][1], a0, bA[1], bA[3]);
        mma_bf16(acc[0][2], a0, bB[0], bB[2]);
        mma_bf16(acc[0][3], a0, bB[1], bB[3]);
        mma_bf16(acc[1][0], a1, bA[0], bA[2]);
        mma_bf16(acc[1][1], a1, bA[1], bA[3]);
        mma_bf16(acc[1][2], a1, bB[0], bB[2]);
        mma_bf16(acc[1][3], a1, bB[1], bB[3]);
    }
    #pragma unroll
    for (int mt = 0; mt < 2; mt++) {
        float sA = 0.f, sB = 0.f;
        #pragma unroll
        for (int nt = 0; nt < 4; nt++) {
            sA += __expf(acc[mt][nt][0]) + __expf(acc[mt][nt][1]);
            sB += __expf(acc[mt][nt][2]) + __expf(acc[mt][nt][3]);
        }
        sA += __shfl_xor_sync(0xffffffffu, sA, 1);
        sA += __shfl_xor_sync(0xffffffffu, sA, 2);
        sB += __shfl_xor_sync(0xffffffffu, sB, 1);
        sB += __shfl_xor_sync(0xffffffffu, sB, 2);
        if ((lane & 3) == 0) {
            int row = rbase + m0 + mt*16 + (lane >> 2);
            if (row < NROWS)     atomicAdd(&g_sumexp[row], sA);
            if (row + 8 < NROWS) atomicAdd(&g_sumexp[row + 8], sB);
        }
    }
}

// ---------------- final loss -------------------------------------------------------
__global__ void loss_kernel(const int* __restrict__ tgt_lens, float* out) {
    int r = blockIdx.x*blockDim.x + threadIdx.x;
    if (r >= NROWS) return;
    int t = r / B_, b = r % B_;
    if (t < tgt_lens[b] - 1) {
        float nll = logf(g_sumexp[r]) - g_lbl[r];
        atomicAdd(out, nll);
    }
}

// ---------------- launch -------------------------------------------------------------
extern "C" void kernel_launch(void* const* d_in, const int* in_sizes, int n_in,
                              void* d_out, int out_size) {
    const float* encoded   = (const float*)d_in[0];
    const float* enc_state = (const float*)d_in[1];
    const int*   tok       = (const int*)  d_in[2];
    const int*   enc_lens  = (const int*)  d_in[3];
    const int*   tgt_lens  = (const int*)  d_in[4];
    const float* E         = (const float*)d_in[5];
    const float* P         = (const float*)d_in[6];
    const float* W0        = (const float*)d_in[7];
    const float* U0        = (const float*)d_in[8];
    const float* b0        = (const float*)d_in[9];
    const float* W1        = (const float*)d_in[10];
    const float* U1        = (const float*)d_in[11];
    const float* b1        = (const float*)d_in[12];
    const float* Wo        = (const float*)d_in[13];
    const float* bo        = (const float*)d_in[14];
    float* out = (float*)d_out;

    convert_kernel<<<(CVT_TOT/4 + 255)/256, 256>>>(W0, U0, W1, U1, E);
    embed_kernel<<<NROWS, 128>>>(E, P, tok);
    init_kernel<<<128, 256>>>(enc_state, out);

    for (int t = 0; t < TM1; t++) {
        gates_mma<<<dim3(64, 4), 128>>>(0);
        lstm_cell<<<32, 256>>>(t, 0, b0);
        gates_mma<<<dim3(64, 4), 128>>>(1);
        lstm_cell<<<32, 256>>>(t, 1, b1);
        attn_kernel<<<B_, 256>>>(t, encoded, enc_lens);
    }

    hproj_gemm<<<dim3(4, 47), 256>>>(Wo, bo);
    tmp_gemm<<<dim3(4, 47), 256>>>(P);
    label_kernel<<<188, 256>>>(tok, E);
    sumexp_mma<<<dim3(500, 24), 128>>>();
    loss_kernel<<<6, 256>>>(tgt_lens, out);
}